// round 1
// baseline (speedup 1.0000x reference)
#include <cuda_runtime.h>
#include <math.h>

#define N_NODES 20000
#define N_EDGES 600000
#define HDIM 128
#define KIN 256
#define NHEADS 4
#define TILE 64
#define TP 132   // padded pitch (floats) for 128-wide intermediate tiles

// ---------------- scratch (static device globals; no allocation) -------------
__device__ float    g_P[N_NODES * HDIM];          // h_V @ Wb1v^T + bb1
__device__ float    g_num[N_NODES * HDIM];        // sum exp(w-m) * V
__device__ float    g_den[N_NODES * NHEADS];      // sum exp(w-m)
__device__ unsigned g_menc[N_NODES * NHEADS];     // ordered-encoded max logit
__device__ float    g_wlog[(size_t)N_EDGES * NHEADS]; // per-edge head logits

// ---------------- helpers ----------------------------------------------------
__device__ __forceinline__ float gelu_f(float x) {
    return 0.5f * x * (1.0f + erff(x * 0.70710678118654752440f));
}
// order-preserving float<->uint for atomicMax (handles negatives)
__device__ __forceinline__ unsigned fenc(float x) {
    unsigned b = __float_as_uint(x);
    return (b & 0x80000000u) ? ~b : (b | 0x80000000u);
}
__device__ __forceinline__ float fdec(unsigned e) {
    return __uint_as_float((e & 0x80000000u) ? (e & 0x7FFFFFFFu) : ~e);
}
#define ENC_NEG_INF 0x007FFFFFu   // fenc(-inf)

// Register-blocked stage: thread j holds hidden unit j for all TILE rows.
// Inner body: 1 broadcast LDS.128 + 4 FFMA per (row, k4). XP compile-time so
// shared offsets fold into immediates.
template<int K, int XP>
__device__ __forceinline__ void gemm_stage(float acc[TILE],
                                           const float* __restrict__ wrow,
                                           const float* __restrict__ xs) {
#pragma unroll 1
    for (int k = 0; k < K; k += 4) {
        float4 wv = *reinterpret_cast<const float4*>(wrow + k);
#pragma unroll
        for (int e = 0; e < TILE; ++e) {
            float4 xv = *reinterpret_cast<const float4*>(xs + e * XP + k);
            acc[e] = fmaf(wv.x, xv.x, acc[e]);
            acc[e] = fmaf(wv.y, xv.y, acc[e]);
            acc[e] = fmaf(wv.z, xv.z, acc[e]);
            acc[e] = fmaf(wv.w, xv.w, acc[e]);
        }
    }
}

// ---------------- kernels ----------------------------------------------------
extern "C" __global__ void __launch_bounds__(128)
k_init() {
    int i = blockIdx.x * blockDim.x + threadIdx.x;
    if (i < N_NODES * HDIM) g_num[i] = 0.0f;
    if (i < N_NODES * NHEADS) { g_den[i] = 0.0f; g_menc[i] = ENC_NEG_INF; }
}

// P = h_V @ Wb1[:, :128]^T + bb1   (per node, 30x cheaper than per edge)
extern "C" __global__ void __launch_bounds__(128)
k_pre(const float* __restrict__ hV, const float* __restrict__ Wb1,
      const float* __restrict__ bb1) {
    __shared__ float xs[TILE * HDIM];
    int j  = threadIdx.x;
    int n0 = blockIdx.x * TILE;
    int cnt = N_NODES - n0; if (cnt > TILE) cnt = TILE;

    const float4* src = reinterpret_cast<const float4*>(hV + (size_t)n0 * HDIM);
    float4* dst = reinterpret_cast<float4*>(xs);
    for (int i = j; i < TILE * HDIM / 4; i += 128) {
        int n = i / (HDIM / 4);
        dst[i] = (n < cnt) ? src[i] : make_float4(0.f, 0.f, 0.f, 0.f);
    }
    __syncthreads();

    float acc[TILE];
    float b = bb1[j];
#pragma unroll
    for (int e = 0; e < TILE; ++e) acc[e] = b;
    gemm_stage<HDIM, HDIM>(acc, Wb1 + j * 384, xs);   // Wb1 row stride 384
#pragma unroll
    for (int e = 0; e < TILE; ++e)
        if (e < cnt) g_P[(size_t)(n0 + e) * HDIM + j] = acc[e];
}

// Bias MLP per edge: t1=gelu(P[c]+hE@Wb1e^T); t2=gelu(t1@Wb2^T+bb2);
// w=(t2@Wb3^T+bb3)/sqrt(32); store w; atomicMax per (node, head).
extern "C" __global__ void __launch_bounds__(128)
k_bias(const float* __restrict__ hE, const int* __restrict__ cid,
       const float* __restrict__ Wb1, const float* __restrict__ Wb2,
       const float* __restrict__ bb2, const float* __restrict__ Wb3,
       const float* __restrict__ bb3) {
    extern __shared__ float sm[];
    float* xs  = sm;                       // TILE*KIN, later reused as t2s
    float* t1s = sm + TILE * KIN;          // TILE*TP
    int*   ce  = (int*)(sm + TILE * KIN + TILE * TP);

    int j = threadIdx.x;
    size_t e0 = (size_t)blockIdx.x * TILE;
    if (j < TILE) ce[j] = cid[e0 + j];
    {
        const float4* src = reinterpret_cast<const float4*>(hE + e0 * KIN);
        float4* dst = reinterpret_cast<float4*>(xs);
        for (int i = j; i < TILE * KIN / 4; i += 128) dst[i] = src[i];
    }
    __syncthreads();

    float acc[TILE];
#pragma unroll
    for (int e = 0; e < TILE; ++e)
        acc[e] = g_P[(size_t)ce[e] * HDIM + j];                 // P[c] (+bb1)
    gemm_stage<KIN, KIN>(acc, Wb1 + j * 384 + HDIM, xs);        // + hE @ Wb1e^T
#pragma unroll
    for (int e = 0; e < TILE; ++e) t1s[e * TP + j] = gelu_f(acc[e]);
    __syncthreads();

    float b2 = bb2[j];
#pragma unroll
    for (int e = 0; e < TILE; ++e) acc[e] = b2;
    gemm_stage<HDIM, TP>(acc, Wb2 + j * HDIM, t1s);
    float* t2s = xs;                                            // overlay
#pragma unroll
    for (int e = 0; e < TILE; ++e) t2s[e * TP + j] = gelu_f(acc[e]);
    __syncthreads();

    const float rs = 0.17677669529663687f;  // 1/sqrt(32)
#pragma unroll
    for (int rep = 0; rep < 2; ++rep) {
        int e = (j >> 2) + rep * 32;
        int h = j & 3;
        const float* w3 = Wb3 + h * HDIM;
        const float* t2 = t2s + e * TP;
        float s = bb3[h];
#pragma unroll
        for (int k = 0; k < HDIM; k += 4) {
            float4 wv = *(const float4*)(w3 + k);
            float4 xv = *(const float4*)(t2 + k);
            s = fmaf(wv.x, xv.x, s); s = fmaf(wv.y, xv.y, s);
            s = fmaf(wv.z, xv.z, s); s = fmaf(wv.w, xv.w, s);
        }
        float w = s * rs;
        g_wlog[(e0 + e) * NHEADS + h] = w;
        atomicMax(&g_menc[(size_t)ce[e] * NHEADS + h], fenc(w));
    }
}

// Value MLP per edge + exp-weighted scatter (unnormalized numerator + denom).
extern "C" __global__ void __launch_bounds__(128)
k_value(const float* __restrict__ hE, const int* __restrict__ cid,
        const float* __restrict__ Wv1, const float* __restrict__ bv1,
        const float* __restrict__ Wv2, const float* __restrict__ bv2,
        const float* __restrict__ Wv3, const float* __restrict__ bv3) {
    extern __shared__ float sm[];
    float* xs  = sm;
    float* t1s = sm + TILE * KIN;
    int*   ce  = (int*)(sm + TILE * KIN + TILE * TP);

    int j = threadIdx.x;
    size_t e0 = (size_t)blockIdx.x * TILE;
    if (j < TILE) ce[j] = cid[e0 + j];
    {
        const float4* src = reinterpret_cast<const float4*>(hE + e0 * KIN);
        float4* dst = reinterpret_cast<float4*>(xs);
        for (int i = j; i < TILE * KIN / 4; i += 128) dst[i] = src[i];
    }
    __syncthreads();

    float acc[TILE];
    float b = bv1[j];
#pragma unroll
    for (int e = 0; e < TILE; ++e) acc[e] = b;
    gemm_stage<KIN, KIN>(acc, Wv1 + j * KIN, xs);
#pragma unroll
    for (int e = 0; e < TILE; ++e) t1s[e * TP + j] = gelu_f(acc[e]);
    __syncthreads();

    b = bv2[j];
#pragma unroll
    for (int e = 0; e < TILE; ++e) acc[e] = b;
    gemm_stage<HDIM, TP>(acc, Wv2 + j * HDIM, t1s);
    float* t2s = xs;
#pragma unroll
    for (int e = 0; e < TILE; ++e) t2s[e * TP + j] = gelu_f(acc[e]);
    __syncthreads();

    b = bv3[j];
#pragma unroll
    for (int e = 0; e < TILE; ++e) acc[e] = b;
    gemm_stage<HDIM, TP>(acc, Wv3 + j * HDIM, t2s);   // V in acc, no gelu

    int h = j >> 5;
#pragma unroll
    for (int e = 0; e < TILE; ++e) {
        int c = ce[e];
        float m  = fdec(g_menc[(size_t)c * NHEADS + h]);
        float w  = g_wlog[(e0 + e) * NHEADS + h];
        float ew = expf(w - m);
        atomicAdd(&g_num[(size_t)c * HDIM + j], ew * acc[e]);
        if ((j & 31) == 0) atomicAdd(&g_den[(size_t)c * NHEADS + h], ew);
    }
}

// agg = num/den; out = agg @ Wo^T
extern "C" __global__ void __launch_bounds__(128)
k_out(const float* __restrict__ Wo, float* __restrict__ out) {
    __shared__ float xs[TILE * HDIM];
    int j  = threadIdx.x;
    int n0 = blockIdx.x * TILE;
    int cnt = N_NODES - n0; if (cnt > TILE) cnt = TILE;

    for (int i = j; i < TILE * HDIM; i += 128) {
        int n = i >> 7, c = i & 127;
        float v = 0.f;
        if (n < cnt) {
            float d  = g_den[(size_t)(n0 + n) * NHEADS + (c >> 5)];
            float nm = g_num[(size_t)(n0 + n) * HDIM + c];
            v = (d > 0.f) ? nm / d : 0.f;   // zero-degree node -> 0
        }
        xs[i] = v;
    }
    __syncthreads();

    float acc[TILE];
#pragma unroll
    for (int e = 0; e < TILE; ++e) acc[e] = 0.f;
    gemm_stage<HDIM, HDIM>(acc, Wo + j * HDIM, xs);
#pragma unroll
    for (int e = 0; e < TILE; ++e)
        if (e < cnt) out[(size_t)(n0 + e) * HDIM + j] = acc[e];
}

// ---------------- launch ------------------------------------------------------
extern "C" void kernel_launch(void* const* d_in, const int* in_sizes, int n_in,
                              void* d_out, int out_size) {
    const float* hV  = (const float*)d_in[0];
    const float* hE  = (const float*)d_in[1];
    const float* Wv1 = (const float*)d_in[2];
    const float* bv1 = (const float*)d_in[3];
    const float* Wv2 = (const float*)d_in[4];
    const float* bv2 = (const float*)d_in[5];
    const float* Wv3 = (const float*)d_in[6];
    const float* bv3 = (const float*)d_in[7];
    const float* Wb1 = (const float*)d_in[8];
    const float* bb1 = (const float*)d_in[9];
    const float* Wb2 = (const float*)d_in[10];
    const float* bb2 = (const float*)d_in[11];
    const float* Wb3 = (const float*)d_in[12];
    const float* bb3 = (const float*)d_in[13];
    const float* Wo  = (const float*)d_in[14];
    const int*   cid = (const int*)d_in[15];
    float* out = (float*)d_out;

    const int smemB = (TILE * KIN + TILE * TP) * 4 + TILE * 4;  // 99584 B
    cudaFuncSetAttribute(k_bias,  cudaFuncAttributeMaxDynamicSharedMemorySize, smemB);
    cudaFuncSetAttribute(k_value, cudaFuncAttributeMaxDynamicSharedMemorySize, smemB);

    k_init<<<(N_NODES * HDIM + 127) / 128, 128>>>();
    k_pre <<<(N_NODES + TILE - 1) / TILE, 128>>>(hV, Wb1, bb1);
    k_bias<<<N_EDGES / TILE, 128, smemB>>>(hE, cid, Wb1, Wb2, bb2, Wb3, bb3);
    k_value<<<N_EDGES / TILE, 128, smemB>>>(hE, cid, Wv1, bv1, Wv2, bv2, Wv3, bv3);
    k_out <<<(N_NODES + TILE - 1) / TILE, 128>>>(Wo, out);
}

// round 4
// speedup vs baseline: 1.0001x; 1.0001x over previous
#include <cuda_runtime.h>
#include <math.h>

#define N_NODES 20000
#define N_EDGES 600000
#define HDIM 128
#define KIN 256
#define NHEADS 4
#define TILE 64
#define TP 132   // padded pitch (floats) for 128-wide intermediate tiles

// ---------------- scratch (static device globals; no allocation) -------------
__device__ float    g_P[N_NODES * HDIM];          // h_V @ Wb1v^T + bb1
__device__ float    g_num[N_NODES * HDIM];        // sum exp(w-m) * V
__device__ float    g_den[N_NODES * NHEADS];      // sum exp(w-m)
__device__ unsigned g_menc[N_NODES * NHEADS];     // ordered-encoded max logit
__device__ float    g_wlog[(size_t)N_EDGES * NHEADS]; // per-edge head logits

// ---------------- helpers ----------------------------------------------------
__device__ __forceinline__ float gelu_f(float x) {
    return 0.5f * x * (1.0f + erff(x * 0.70710678118654752440f));
}
// order-preserving float<->uint for atomicMax (handles negatives)
__device__ __forceinline__ unsigned fenc(float x) {
    unsigned b = __float_as_uint(x);
    return (b & 0x80000000u) ? ~b : (b | 0x80000000u);
}
__device__ __forceinline__ float fdec(unsigned e) {
    return __uint_as_float((e & 0x80000000u) ? (e & 0x7FFFFFFFu) : ~e);
}
#define ENC_NEG_INF 0x007FFFFFu   // fenc(-inf)

// Register-blocked stage: thread j holds hidden unit j for all TILE rows.
// Inner body: 1 broadcast LDS.128 + 4 FFMA per (row, k4). XP compile-time so
// shared offsets fold into immediates.
template<int K, int XP>
__device__ __forceinline__ void gemm_stage(float acc[TILE],
                                           const float* __restrict__ wrow,
                                           const float* __restrict__ xs) {
#pragma unroll 1
    for (int k = 0; k < K; k += 4) {
        float4 wv = *reinterpret_cast<const float4*>(wrow + k);
#pragma unroll
        for (int e = 0; e < TILE; ++e) {
            float4 xv = *reinterpret_cast<const float4*>(xs + e * XP + k);
            acc[e] = fmaf(wv.x, xv.x, acc[e]);
            acc[e] = fmaf(wv.y, xv.y, acc[e]);
            acc[e] = fmaf(wv.z, xv.z, acc[e]);
            acc[e] = fmaf(wv.w, xv.w, acc[e]);
        }
    }
}

// ---------------- kernels ----------------------------------------------------
extern "C" __global__ void __launch_bounds__(128)
k_init() {
    int i = blockIdx.x * blockDim.x + threadIdx.x;
    if (i < N_NODES * HDIM) g_num[i] = 0.0f;
    if (i < N_NODES * NHEADS) { g_den[i] = 0.0f; g_menc[i] = ENC_NEG_INF; }
}

// P = h_V @ Wb1[:, :128]^T + bb1   (per node, 30x cheaper than per edge)
extern "C" __global__ void __launch_bounds__(128)
k_pre(const float* __restrict__ hV, const float* __restrict__ Wb1,
      const float* __restrict__ bb1) {
    __shared__ float xs[TILE * HDIM];
    int j  = threadIdx.x;
    int n0 = blockIdx.x * TILE;
    int cnt = N_NODES - n0; if (cnt > TILE) cnt = TILE;

    const float4* src = reinterpret_cast<const float4*>(hV + (size_t)n0 * HDIM);
    float4* dst = reinterpret_cast<float4*>(xs);
    for (int i = j; i < TILE * HDIM / 4; i += 128) {
        int n = i / (HDIM / 4);
        dst[i] = (n < cnt) ? src[i] : make_float4(0.f, 0.f, 0.f, 0.f);
    }
    __syncthreads();

    float acc[TILE];
    float b = bb1[j];
#pragma unroll
    for (int e = 0; e < TILE; ++e) acc[e] = b;
    gemm_stage<HDIM, HDIM>(acc, Wb1 + j * 384, xs);   // Wb1 row stride 384
#pragma unroll
    for (int e = 0; e < TILE; ++e)
        if (e < cnt) g_P[(size_t)(n0 + e) * HDIM + j] = acc[e];
}

// Bias MLP per edge: t1=gelu(P[c]+hE@Wb1e^T); t2=gelu(t1@Wb2^T+bb2);
// w=(t2@Wb3^T+bb3)/sqrt(32); store w; atomicMax per (node, head).
extern "C" __global__ void __launch_bounds__(128)
k_bias(const float* __restrict__ hE, const int* __restrict__ cid,
       const float* __restrict__ Wb1, const float* __restrict__ Wb2,
       const float* __restrict__ bb2, const float* __restrict__ Wb3,
       const float* __restrict__ bb3) {
    extern __shared__ float sm[];
    float* xs  = sm;                       // TILE*KIN, later reused as t2s
    float* t1s = sm + TILE * KIN;          // TILE*TP
    int*   ce  = (int*)(sm + TILE * KIN + TILE * TP);

    int j = threadIdx.x;
    size_t e0 = (size_t)blockIdx.x * TILE;
    if (j < TILE) ce[j] = cid[e0 + j];
    {
        const float4* src = reinterpret_cast<const float4*>(hE + e0 * KIN);
        float4* dst = reinterpret_cast<float4*>(xs);
        for (int i = j; i < TILE * KIN / 4; i += 128) dst[i] = src[i];
    }
    __syncthreads();

    float acc[TILE];
#pragma unroll
    for (int e = 0; e < TILE; ++e)
        acc[e] = g_P[(size_t)ce[e] * HDIM + j];                 // P[c] (+bb1)
    gemm_stage<KIN, KIN>(acc, Wb1 + j * 384 + HDIM, xs);        // + hE @ Wb1e^T
#pragma unroll
    for (int e = 0; e < TILE; ++e) t1s[e * TP + j] = gelu_f(acc[e]);
    __syncthreads();

    float b2 = bb2[j];
#pragma unroll
    for (int e = 0; e < TILE; ++e) acc[e] = b2;
    gemm_stage<HDIM, TP>(acc, Wb2 + j * HDIM, t1s);
    float* t2s = xs;                                            // overlay
#pragma unroll
    for (int e = 0; e < TILE; ++e) t2s[e * TP + j] = gelu_f(acc[e]);
    __syncthreads();

    const float rs = 0.17677669529663687f;  // 1/sqrt(32)
#pragma unroll
    for (int rep = 0; rep < 2; ++rep) {
        int e = (j >> 2) + rep * 32;
        int h = j & 3;
        const float* w3 = Wb3 + h * HDIM;
        const float* t2 = t2s + e * TP;
        float s = bb3[h];
#pragma unroll
        for (int k = 0; k < HDIM; k += 4) {
            float4 wv = *(const float4*)(w3 + k);
            float4 xv = *(const float4*)(t2 + k);
            s = fmaf(wv.x, xv.x, s); s = fmaf(wv.y, xv.y, s);
            s = fmaf(wv.z, xv.z, s); s = fmaf(wv.w, xv.w, s);
        }
        float w = s * rs;
        g_wlog[(e0 + e) * NHEADS + h] = w;
        atomicMax(&g_menc[(size_t)ce[e] * NHEADS + h], fenc(w));
    }
}

// Value MLP per edge + exp-weighted scatter (unnormalized numerator + denom).
extern "C" __global__ void __launch_bounds__(128)
k_value(const float* __restrict__ hE, const int* __restrict__ cid,
        const float* __restrict__ Wv1, const float* __restrict__ bv1,
        const float* __restrict__ Wv2, const float* __restrict__ bv2,
        const float* __restrict__ Wv3, const float* __restrict__ bv3) {
    extern __shared__ float sm[];
    float* xs  = sm;
    float* t1s = sm + TILE * KIN;
    int*   ce  = (int*)(sm + TILE * KIN + TILE * TP);

    int j = threadIdx.x;
    size_t e0 = (size_t)blockIdx.x * TILE;
    if (j < TILE) ce[j] = cid[e0 + j];
    {
        const float4* src = reinterpret_cast<const float4*>(hE + e0 * KIN);
        float4* dst = reinterpret_cast<float4*>(xs);
        for (int i = j; i < TILE * KIN / 4; i += 128) dst[i] = src[i];
    }
    __syncthreads();

    float acc[TILE];
    float b = bv1[j];
#pragma unroll
    for (int e = 0; e < TILE; ++e) acc[e] = b;
    gemm_stage<KIN, KIN>(acc, Wv1 + j * KIN, xs);
#pragma unroll
    for (int e = 0; e < TILE; ++e) t1s[e * TP + j] = gelu_f(acc[e]);
    __syncthreads();

    b = bv2[j];
#pragma unroll
    for (int e = 0; e < TILE; ++e) acc[e] = b;
    gemm_stage<HDIM, TP>(acc, Wv2 + j * HDIM, t1s);
    float* t2s = xs;
#pragma unroll
    for (int e = 0; e < TILE; ++e) t2s[e * TP + j] = gelu_f(acc[e]);
    __syncthreads();

    b = bv3[j];
#pragma unroll
    for (int e = 0; e < TILE; ++e) acc[e] = b;
    gemm_stage<HDIM, TP>(acc, Wv3 + j * HDIM, t2s);   // V in acc, no gelu

    int h = j >> 5;
#pragma unroll
    for (int e = 0; e < TILE; ++e) {
        int c = ce[e];
        float m  = fdec(g_menc[(size_t)c * NHEADS + h]);
        float w  = g_wlog[(e0 + e) * NHEADS + h];
        float ew = expf(w - m);
        atomicAdd(&g_num[(size_t)c * HDIM + j], ew * acc[e]);
        if ((j & 31) == 0) atomicAdd(&g_den[(size_t)c * NHEADS + h], ew);
    }
}

// agg = num/den; out = agg @ Wo^T
extern "C" __global__ void __launch_bounds__(128)
k_out(const float* __restrict__ Wo, float* __restrict__ out) {
    __shared__ float xs[TILE * HDIM];
    int j  = threadIdx.x;
    int n0 = blockIdx.x * TILE;
    int cnt = N_NODES - n0; if (cnt > TILE) cnt = TILE;

    for (int i = j; i < TILE * HDIM; i += 128) {
        int n = i >> 7, c = i & 127;
        float v = 0.f;
        if (n < cnt) {
            float d  = g_den[(size_t)(n0 + n) * NHEADS + (c >> 5)];
            float nm = g_num[(size_t)(n0 + n) * HDIM + c];
            v = (d > 0.f) ? nm / d : 0.f;   // zero-degree node -> 0
        }
        xs[i] = v;
    }
    __syncthreads();

    float acc[TILE];
#pragma unroll
    for (int e = 0; e < TILE; ++e) acc[e] = 0.f;
    gemm_stage<HDIM, HDIM>(acc, Wo + j * HDIM, xs);
#pragma unroll
    for (int e = 0; e < TILE; ++e)
        if (e < cnt) out[(size_t)(n0 + e) * HDIM + j] = acc[e];
}

// ---------------- launch ------------------------------------------------------
extern "C" void kernel_launch(void* const* d_in, const int* in_sizes, int n_in,
                              void* d_out, int out_size) {
    const float* hV  = (const float*)d_in[0];
    const float* hE  = (const float*)d_in[1];
    const float* Wv1 = (const float*)d_in[2];
    const float* bv1 = (const float*)d_in[3];
    const float* Wv2 = (const float*)d_in[4];
    const float* bv2 = (const float*)d_in[5];
    const float* Wv3 = (const float*)d_in[6];
    const float* bv3 = (const float*)d_in[7];
    const float* Wb1 = (const float*)d_in[8];
    const float* bb1 = (const float*)d_in[9];
    const float* Wb2 = (const float*)d_in[10];
    const float* bb2 = (const float*)d_in[11];
    const float* Wb3 = (const float*)d_in[12];
    const float* bb3 = (const float*)d_in[13];
    const float* Wo  = (const float*)d_in[14];
    const int*   cid = (const int*)d_in[15];
    float* out = (float*)d_out;

    const int smemB = (TILE * KIN + TILE * TP) * 4 + TILE * 4;  // 99584 B
    cudaFuncSetAttribute(k_bias,  cudaFuncAttributeMaxDynamicSharedMemorySize, smemB);
    cudaFuncSetAttribute(k_value, cudaFuncAttributeMaxDynamicSharedMemorySize, smemB);

    k_init<<<(N_NODES * HDIM + 127) / 128, 128>>>();
    k_pre <<<(N_NODES + TILE - 1) / TILE, 128>>>(hV, Wb1, bb1);
    k_bias<<<N_EDGES / TILE, 128, smemB>>>(hE, cid, Wb1, Wb2, bb2, Wb3, bb3);
    k_value<<<N_EDGES / TILE, 128, smemB>>>(hE, cid, Wv1, bv1, Wv2, bv2, Wv3, bv3);
    k_out <<<(N_NODES + TILE - 1) / TILE, 128>>>(Wo, out);
}

// round 6
// speedup vs baseline: 2.7821x; 2.7818x over previous
#include <cuda_runtime.h>
#include <cuda_bf16.h>
#include <math.h>
#include <cstdint>

#define N_NODES 20000
#define N_EDGES 600000
#define HDIM 128
#define NHEADS 4

// ---------------- scratch -----------------------------------------------------
__device__ float    g_P[N_NODES * HDIM];
__device__ float    g_num[N_NODES * HDIM];
__device__ float    g_den[N_NODES * NHEADS];
__device__ unsigned g_menc[N_NODES * NHEADS];
__device__ float    g_wlog[(size_t)N_EDGES * NHEADS];

__device__ __align__(16) __nv_bfloat16 g_wv1h[32768], g_wv1l[32768];
__device__ __align__(16) __nv_bfloat16 g_wv2h[16384], g_wv2l[16384];
__device__ __align__(16) __nv_bfloat16 g_wv3h[16384], g_wv3l[16384];
__device__ __align__(16) __nv_bfloat16 g_wb1h[32768], g_wb1l[32768];
__device__ __align__(16) __nv_bfloat16 g_wb2h[16384], g_wb2l[16384];
__device__ __align__(16) __nv_bfloat16 g_wb3h[2048],  g_wb3l[2048];

// ---------------- helpers -----------------------------------------------------
__device__ __forceinline__ float gelu_f(float x) {
    return 0.5f * x * (1.0f + erff(x * 0.70710678118654752440f));
}
__device__ __forceinline__ unsigned fenc(float x) {
    unsigned b = __float_as_uint(x);
    return (b & 0x80000000u) ? ~b : (b | 0x80000000u);
}
__device__ __forceinline__ float fdec(unsigned e) {
    return __uint_as_float((e & 0x80000000u) ? (e & 0x7FFFFFFFu) : ~e);
}
#define ENC_NEG_INF 0x007FFFFFu

__device__ __forceinline__ void split2(float a, float b, unsigned &hi, unsigned &lo) {
    __nv_bfloat16 ha = __float2bfloat16(a), hb = __float2bfloat16(b);
    float ra = a - __bfloat162float(ha), rb = b - __bfloat162float(hb);
    __nv_bfloat162 th; th.x = ha; th.y = hb;
    __nv_bfloat162 tl = __floats2bfloat162_rn(ra, rb);
    hi = *reinterpret_cast<unsigned*>(&th);
    lo = *reinterpret_cast<unsigned*>(&tl);
}
__device__ __forceinline__ uint32_t smem_to_u32(const void* p) {
    uint32_t a;
    asm("{ .reg .u64 t; cvta.to.shared.u64 t, %1; cvt.u32.u64 %0, t; }" : "=r"(a) : "l"(p));
    return a;
}
__device__ __forceinline__ unsigned sw128(unsigned byte) {
    return byte ^ ((byte >> 3) & 0x70);
}

// ---------------- mma.sync primitives (base ISA, no 'a' features) --------------
__device__ __forceinline__ void ldsm4(unsigned r[4], uint32_t addr) {
    asm volatile("ldmatrix.sync.aligned.m8n8.x4.shared.b16 {%0,%1,%2,%3}, [%4];"
        : "=r"(r[0]), "=r"(r[1]), "=r"(r[2]), "=r"(r[3]) : "r"(addr));
}
__device__ __forceinline__ void mma_bf16(float c[4], const unsigned a[4], const unsigned b[2]) {
    asm volatile("mma.sync.aligned.m16n8k16.row.col.f32.bf16.bf16.f32 "
        "{%0,%1,%2,%3}, {%4,%5,%6,%7}, {%8,%9}, {%0,%1,%2,%3};"
        : "+f"(c[0]), "+f"(c[1]), "+f"(c[2]), "+f"(c[3])
        : "r"(a[0]), "r"(a[1]), "r"(a[2]), "r"(a[3]), "r"(b[0]), "r"(b[1]));
}

// smem byte offsets (dynamic)
#define OFF_CE   0
#define OFF_SEW  512
#define OFF_AB   4096
#define OFF_T0   69632
#define OFF_T1   135168
#define SMEM_MM  200704

// accumulate one K=64 chunk: 3-term split (hh, hl, lh). Tiles are 128-row x 64-col
// bf16 SW128 (128B pitch). Warp tile 64x32: wm in {0,1}, wn in {0..3}.
__device__ __forceinline__ void chunk_mma(float acc[4][4][4],
                                          uint32_t Ah, uint32_t Al,
                                          uint32_t Bh, uint32_t Bl,
                                          int wm, int wn, int lid) {
    int g = lid >> 3, r = lid & 7;
    int am = (g & 1) * 8 + r, ak = (g >> 1) * 8;   // A ldsm row/col within subtile
    int bn = (g >> 1) * 8 + r, bk = (g & 1) * 8;   // B ldsm row/col
#pragma unroll
    for (int ks = 0; ks < 4; ++ks) {
        int kb = ks * 16;
        unsigned Af[2][4][4], Bf[2][4][2];
#pragma unroll
        for (int s = 0; s < 2; ++s) {
            uint32_t Ab = s ? Al : Ah;
#pragma unroll
            for (int ms = 0; ms < 4; ++ms) {
                unsigned byte = (unsigned)((wm * 64 + ms * 16 + am) * 128 + (kb + ak) * 2);
                ldsm4(Af[s][ms], Ab + sw128(byte));
            }
            uint32_t Bb = s ? Bl : Bh;
#pragma unroll
            for (int np = 0; np < 2; ++np) {
                unsigned byte = (unsigned)((wn * 32 + np * 16 + bn) * 128 + (kb + bk) * 2);
                unsigned t[4];
                ldsm4(t, Bb + sw128(byte));
                Bf[s][np*2][0] = t[0]; Bf[s][np*2][1] = t[1];
                Bf[s][np*2+1][0] = t[2]; Bf[s][np*2+1][1] = t[3];
            }
        }
#pragma unroll
        for (int ms = 0; ms < 4; ++ms)
#pragma unroll
            for (int ns = 0; ns < 4; ++ns) {
                mma_bf16(acc[ms][ns], Af[0][ms], Bf[0][ns]);   // hh
                mma_bf16(acc[ms][ns], Af[0][ms], Bf[1][ns]);   // hl
                mma_bf16(acc[ms][ns], Af[1][ms], Bf[0][ns]);   // lh
            }
    }
}

// logits variant: only n-subtile 0 (n0-7), B tile is 16-row padded Wb3 chunk
__device__ __forceinline__ void chunk_mma_log(float accl[4][4],
                                              uint32_t Ah, uint32_t Al,
                                              uint32_t Bh, uint32_t Bl,
                                              int wm, int lid) {
    int g = lid >> 3, r = lid & 7;
    int am = (g & 1) * 8 + r, ak = (g >> 1) * 8;
    int bn = (g >> 1) * 8 + r, bk = (g & 1) * 8;
#pragma unroll
    for (int ks = 0; ks < 4; ++ks) {
        int kb = ks * 16;
        unsigned Af[2][4][4], Bf[2][2];
#pragma unroll
        for (int s = 0; s < 2; ++s) {
            uint32_t Ab = s ? Al : Ah;
#pragma unroll
            for (int ms = 0; ms < 4; ++ms) {
                unsigned byte = (unsigned)((wm * 64 + ms * 16 + am) * 128 + (kb + ak) * 2);
                ldsm4(Af[s][ms], Ab + sw128(byte));
            }
            unsigned byte = (unsigned)(bn * 128 + (kb + bk) * 2);
            unsigned t[4];
            ldsm4(t, (s ? Bl : Bh) + sw128(byte));
            Bf[s][0] = t[0]; Bf[s][1] = t[1];
        }
#pragma unroll
        for (int ms = 0; ms < 4; ++ms) {
            mma_bf16(accl[ms], Af[0][ms], Bf[0]);
            mma_bf16(accl[ms], Af[0][ms], Bf[1]);
            mma_bf16(accl[ms], Af[1][ms], Bf[0]);
        }
    }
}

// ---------------- tile loaders (layouts identical to k_wconv output) -----------
__device__ __forceinline__ void loadA(char* buf, const float* __restrict__ hE,
                                      size_t e0, int c, int tid) {
    const float4* hE4 = reinterpret_cast<const float4*>(hE);
    char* AH = buf; char* AL = buf + 16384;
#pragma unroll
    for (int it = 0; it < 8; ++it) {
        int idx = tid + it * 256;
        int m = idx >> 4, q = idx & 15;
        size_t e = e0 + (size_t)m;
        float4 v = make_float4(0.f, 0.f, 0.f, 0.f);
        if (e < N_EDGES) v = hE4[e * 64 + (size_t)(c * 16 + q)];
        unsigned sw = sw128((unsigned)(m * 128 + q * 8));
        unsigned h01, l01, h23, l23;
        split2(v.x, v.y, h01, l01);
        split2(v.z, v.w, h23, l23);
        *(uint2*)(AH + sw) = make_uint2(h01, h23);
        *(uint2*)(AL + sw) = make_uint2(l01, l23);
    }
}
__device__ __forceinline__ void loadB(char* bufB, const __nv_bfloat16* gh,
                                      const __nv_bfloat16* gl, int c, int nq, int tid) {
    const float4* sh = reinterpret_cast<const float4*>(gh) + c * nq;
    const float4* sl = reinterpret_cast<const float4*>(gl) + c * nq;
    float4* dh = (float4*)bufB; float4* dl = (float4*)(bufB + 16384);
    for (int i = tid; i < nq; i += 256) { dh[i] = sh[i]; dl[i] = sl[i]; }
}

// acc + add -> gelu -> split -> T tiles (2 chunks hi @+0/+16K, lo @+32K/+48K)
__device__ __forceinline__ void epi_store(float acc[4][4][4], char* T,
                                          const float* __restrict__ addv,
                                          const int* __restrict__ ce, bool perrow,
                                          int wm, int wn, int lid) {
#pragma unroll
    for (int ms = 0; ms < 4; ++ms) {
        int r0 = wm * 64 + ms * 16 + (lid >> 2), r1 = r0 + 8;
#pragma unroll
        for (int ns = 0; ns < 4; ++ns) {
            int n = wn * 32 + ns * 8 + (lid & 3) * 2;
            const float* a0 = perrow ? (addv + (size_t)ce[r0] * 128 + n) : (addv + n);
            const float* a1 = perrow ? (addv + (size_t)ce[r1] * 128 + n) : (addv + n);
            float o0 = gelu_f(acc[ms][ns][0] + a0[0]);
            float o1 = gelu_f(acc[ms][ns][1] + a0[1]);
            float o2 = gelu_f(acc[ms][ns][2] + a1[0]);
            float o3 = gelu_f(acc[ms][ns][3] + a1[1]);
            unsigned h01, l01, h23, l23;
            split2(o0, o1, h01, l01);
            split2(o2, o3, h23, l23);
            int ch = n >> 6, kk = n & 63;
            unsigned s0 = sw128((unsigned)(r0 * 128 + kk * 2));
            unsigned s1 = sw128((unsigned)(r1 * 128 + kk * 2));
            char* th = T + ch * 16384;
            *(unsigned*)(th + s0) = h01;          *(unsigned*)(th + s1) = h23;
            *(unsigned*)(th + 32768 + s0) = l01;  *(unsigned*)(th + 32768 + s1) = l23;
        }
    }
}

// ---------------- setup kernels -----------------------------------------------
extern "C" __global__ void __launch_bounds__(128)
k_init() {
    int i = blockIdx.x * blockDim.x + threadIdx.x;
    if (i < N_NODES * HDIM) g_num[i] = 0.0f;
    if (i < N_NODES * NHEADS) { g_den[i] = 0.0f; g_menc[i] = ENC_NEG_INF; }
}

extern "C" __global__ void __launch_bounds__(256)
k_wconv(const float* __restrict__ W, __nv_bfloat16* __restrict__ hi,
        __nv_bfloat16* __restrict__ lo, int nrows_pad, int nrows_real,
        int nchunks, int rstride, int coff) {
    int idx = blockIdx.x * 256 + threadIdx.x;
    int tile = nrows_pad * 64;
    if (idx >= tile * nchunks) return;
    int c = idx / tile, rem = idx % tile;
    int n = rem / 64, kk = rem % 64;
    float x = (n < nrows_real) ? W[n * rstride + coff + c * 64 + kk] : 0.0f;
    __nv_bfloat16 h = __float2bfloat16(x);
    float r = x - __bfloat162float(h);
    unsigned sw = sw128((unsigned)(n * 128 + kk * 2));
    hi[c * tile + sw / 2] = h;
    lo[c * tile + sw / 2] = __float2bfloat16(r);
}

template<int K, int XP>
__device__ __forceinline__ void gemm_stage(float acc[64], const float* __restrict__ wrow,
                                           const float* __restrict__ xs) {
#pragma unroll 1
    for (int k = 0; k < K; k += 4) {
        float4 wv = *reinterpret_cast<const float4*>(wrow + k);
#pragma unroll
        for (int e = 0; e < 64; ++e) {
            float4 xv = *reinterpret_cast<const float4*>(xs + e * XP + k);
            acc[e] = fmaf(wv.x, xv.x, acc[e]);
            acc[e] = fmaf(wv.y, xv.y, acc[e]);
            acc[e] = fmaf(wv.z, xv.z, acc[e]);
            acc[e] = fmaf(wv.w, xv.w, acc[e]);
        }
    }
}

extern "C" __global__ void __launch_bounds__(128)
k_pre(const float* __restrict__ hV, const float* __restrict__ Wb1,
      const float* __restrict__ bb1) {
    __shared__ float xs[64 * HDIM];
    int j = threadIdx.x;
    int n0 = blockIdx.x * 64;
    int cnt = N_NODES - n0; if (cnt > 64) cnt = 64;
    const float4* src = reinterpret_cast<const float4*>(hV + (size_t)n0 * HDIM);
    float4* dst = reinterpret_cast<float4*>(xs);
    for (int i = j; i < 64 * HDIM / 4; i += 128) {
        int n = i / (HDIM / 4);
        dst[i] = (n < cnt) ? src[i] : make_float4(0.f, 0.f, 0.f, 0.f);
    }
    __syncthreads();
    float acc[64];
    float b = bb1[j];
#pragma unroll
    for (int e = 0; e < 64; ++e) acc[e] = b;
    gemm_stage<HDIM, HDIM>(acc, Wb1 + j * 384, xs);
#pragma unroll
    for (int e = 0; e < 64; ++e)
        if (e < cnt) g_P[(size_t)(n0 + e) * HDIM + j] = acc[e];
}

// ---------------- unified HMMA edge kernel -------------------------------------
// mode 0 = value MLP (+ exp scatter);  mode 1 = bias MLP (+ logits/atomicMax)
extern "C" __global__ void __launch_bounds__(256)
k_edge_mma(int mode, const float* __restrict__ hE, const int* __restrict__ cid,
           const float* __restrict__ b2, const float* __restrict__ b3,
           const float* __restrict__ b1) {
    extern __shared__ char sm[];
    uint32_t smb = smem_to_u32(sm);
    int tid = threadIdx.x, wid = tid >> 5, lid = tid & 31;
    int wm = wid & 1, wn = wid >> 1;
    size_t e0 = (size_t)blockIdx.x * 128;
    int* ce = (int*)(sm + OFF_CE);
    float* sew = (float*)(sm + OFF_SEW);
    if (tid < 128) ce[tid] = (e0 + tid < N_EDGES) ? cid[e0 + tid] : 0;

    const __nv_bfloat16 *W1h = mode ? g_wb1h : g_wv1h, *W1l = mode ? g_wb1l : g_wv1l;
    const __nv_bfloat16 *W2h = mode ? g_wb2h : g_wv2h, *W2l = mode ? g_wb2l : g_wv2l;

    uint32_t AB = smb + OFF_AB;
    float acc[4][4][4];
#pragma unroll
    for (int i = 0; i < 4; ++i)
#pragma unroll
        for (int j2 = 0; j2 < 4; ++j2)
#pragma unroll
            for (int k = 0; k < 4; ++k) acc[i][j2][k] = 0.f;

    // ---- L1: hE @ W1^T (K=256, 4 chunks) ----
    for (int c = 0; c < 4; ++c) {
        __syncthreads();
        loadA(sm + OFF_AB, hE, e0, c, tid);
        loadB(sm + OFF_AB + 32768, W1h, W1l, c, 1024, tid);
        __syncthreads();
        chunk_mma(acc, AB, AB + 16384, AB + 32768, AB + 49152, wm, wn, lid);
    }
    // t1 = gelu(D + (P[ce] or bv1))
    epi_store(acc, sm + OFF_T0, mode ? g_P : b1, ce, mode != 0, wm, wn, lid);
    __syncthreads();

    // ---- L2: t1 @ W2^T (K=128, 2 chunks) ----
#pragma unroll
    for (int i = 0; i < 4; ++i)
#pragma unroll
        for (int j2 = 0; j2 < 4; ++j2)
#pragma unroll
            for (int k = 0; k < 4; ++k) acc[i][j2][k] = 0.f;
    for (int c = 0; c < 2; ++c) {
        __syncthreads();
        loadB(sm + OFF_AB + 32768, W2h, W2l, c, 1024, tid);
        __syncthreads();
        uint32_t T = smb + OFF_T0 + c * 16384;
        chunk_mma(acc, T, T + 32768, AB + 32768, AB + 49152, wm, wn, lid);
    }
    epi_store(acc, sm + OFF_T1, b2, ce, false, wm, wn, lid);
    __syncthreads();

    // ---- L3 ----
    if (mode) {
        float accl[4][4];
#pragma unroll
        for (int i = 0; i < 4; ++i)
#pragma unroll
            for (int k = 0; k < 4; ++k) accl[i][k] = 0.f;
        for (int c = 0; c < 2; ++c) {
            __syncthreads();
            loadB(sm + OFF_AB + 32768, g_wb3h, g_wb3l, c, 128, tid);
            __syncthreads();
            if (wn == 0) {
                uint32_t T = smb + OFF_T1 + c * 16384;
                chunk_mma_log(accl, T, T + 32768, AB + 32768, AB + 49152, wm, lid);
            }
        }
        if (wn == 0 && (lid & 3) < 2) {
            const float rs = 0.17677669529663687f;  // 1/sqrt(32)
            int n = (lid & 3) * 2;
            float bn0 = b3[n], bn1 = b3[n + 1];
#pragma unroll
            for (int ms = 0; ms < 4; ++ms) {
                int r0 = wm * 64 + ms * 16 + (lid >> 2), r1 = r0 + 8;
                if (e0 + r0 < N_EDGES) {
                    float w0 = (accl[ms][0] + bn0) * rs, w1 = (accl[ms][1] + bn1) * rs;
                    g_wlog[(e0 + r0) * 4 + n] = w0;
                    g_wlog[(e0 + r0) * 4 + n + 1] = w1;
                    atomicMax(&g_menc[(size_t)ce[r0] * 4 + n], fenc(w0));
                    atomicMax(&g_menc[(size_t)ce[r0] * 4 + n + 1], fenc(w1));
                }
                if (e0 + r1 < N_EDGES) {
                    float w2 = (accl[ms][2] + bn0) * rs, w3 = (accl[ms][3] + bn1) * rs;
                    g_wlog[(e0 + r1) * 4 + n] = w2;
                    g_wlog[(e0 + r1) * 4 + n + 1] = w3;
                    atomicMax(&g_menc[(size_t)ce[r1] * 4 + n], fenc(w2));
                    atomicMax(&g_menc[(size_t)ce[r1] * 4 + n + 1], fenc(w3));
                }
            }
        }
    } else {
        // V = t2 @ Wv3^T; then exp-weighted scatter
#pragma unroll
        for (int i = 0; i < 4; ++i)
#pragma unroll
            for (int j2 = 0; j2 < 4; ++j2)
#pragma unroll
                for (int k = 0; k < 4; ++k) acc[i][j2][k] = 0.f;
        for (int c = 0; c < 2; ++c) {
            __syncthreads();
            loadB(sm + OFF_AB + 32768, g_wv3h, g_wv3l, c, 1024, tid);
            __syncthreads();
            uint32_t T = smb + OFF_T1 + c * 16384;
            chunk_mma(acc, T, T + 32768, AB + 32768, AB + 49152, wm, wn, lid);
        }
        // per-edge softmax weights (+ denominator)
        if (tid < 128) {
            bool v = (e0 + tid) < N_EDGES;
            int cn = ce[tid];
#pragma unroll
            for (int h = 0; h < 4; ++h) {
                float ew = 0.f;
                if (v) {
                    float w = g_wlog[(e0 + tid) * 4 + h];
                    float m = fdec(g_menc[(size_t)cn * 4 + h]);
                    ew = expf(w - m);
                    atomicAdd(&g_den[(size_t)cn * 4 + h], ew);
                }
                sew[tid * 4 + h] = ew;
            }
        }
        __syncthreads();
#pragma unroll
        for (int ms = 0; ms < 4; ++ms) {
            int r0 = wm * 64 + ms * 16 + (lid >> 2), r1 = r0 + 8;
            float ew0 = sew[r0 * 4 + wn], ew1 = sew[r1 * 4 + wn];
            bool v0 = (e0 + r0) < N_EDGES, v1 = (e0 + r1) < N_EDGES;
            float* d0 = g_num + (size_t)ce[r0] * 128;
            float* d1 = g_num + (size_t)ce[r1] * 128;
#pragma unroll
            for (int ns = 0; ns < 4; ++ns) {
                int n = wn * 32 + ns * 8 + (lid & 3) * 2;
                float bn0 = b3[n], bn1 = b3[n + 1];
                if (v0) {
                    atomicAdd(d0 + n,     ew0 * (acc[ms][ns][0] + bn0));
                    atomicAdd(d0 + n + 1, ew0 * (acc[ms][ns][1] + bn1));
                }
                if (v1) {
                    atomicAdd(d1 + n,     ew1 * (acc[ms][ns][2] + bn0));
                    atomicAdd(d1 + n + 1, ew1 * (acc[ms][ns][3] + bn1));
                }
            }
        }
    }
}

// ---------------- output projection --------------------------------------------
extern "C" __global__ void __launch_bounds__(128)
k_out(const float* __restrict__ Wo, float* __restrict__ out) {
    __shared__ float xs[64 * HDIM];
    int j = threadIdx.x;
    int n0 = blockIdx.x * 64;
    int cnt = N_NODES - n0; if (cnt > 64) cnt = 64;
    for (int i = j; i < 64 * HDIM; i += 128) {
        int n = i >> 7, c = i & 127;
        float v = 0.f;
        if (n < cnt) {
            float d = g_den[(size_t)(n0 + n) * NHEADS + (c >> 5)];
            float nm = g_num[(size_t)(n0 + n) * HDIM + c];
            v = (d > 0.f) ? nm / d : 0.f;
        }
        xs[i] = v;
    }
    __syncthreads();
    float acc[64];
#pragma unroll
    for (int e = 0; e < 64; ++e) acc[e] = 0.f;
    gemm_stage<HDIM, HDIM>(acc, Wo + j * HDIM, xs);
#pragma unroll
    for (int e = 0; e < 64; ++e)
        if (e < cnt) out[(size_t)(n0 + e) * HDIM + j] = acc[e];
}

// ---------------- launch --------------------------------------------------------
extern "C" void kernel_launch(void* const* d_in, const int* in_sizes, int n_in,
                              void* d_out, int out_size) {
    const float* hV  = (const float*)d_in[0];
    const float* hE  = (const float*)d_in[1];
    const float* Wv1 = (const float*)d_in[2];
    const float* bv1 = (const float*)d_in[3];
    const float* Wv2 = (const float*)d_in[4];
    const float* bv2 = (const float*)d_in[5];
    const float* Wv3 = (const float*)d_in[6];
    const float* bv3 = (const float*)d_in[7];
    const float* Wb1 = (const float*)d_in[8];
    const float* bb1 = (const float*)d_in[9];
    const float* Wb2 = (const float*)d_in[10];
    const float* bb2 = (const float*)d_in[11];
    const float* Wb3 = (const float*)d_in[12];
    const float* bb3 = (const float*)d_in[13];
    const float* Wo  = (const float*)d_in[14];
    const int*   cid = (const int*)d_in[15];
    float* out = (float*)d_out;

    __nv_bfloat16 *wv1h, *wv1l, *wv2h, *wv2l, *wv3h, *wv3l;
    __nv_bfloat16 *wb1h, *wb1l, *wb2h, *wb2l, *wb3h, *wb3l;
    cudaGetSymbolAddress((void**)&wv1h, g_wv1h); cudaGetSymbolAddress((void**)&wv1l, g_wv1l);
    cudaGetSymbolAddress((void**)&wv2h, g_wv2h); cudaGetSymbolAddress((void**)&wv2l, g_wv2l);
    cudaGetSymbolAddress((void**)&wv3h, g_wv3h); cudaGetSymbolAddress((void**)&wv3l, g_wv3l);
    cudaGetSymbolAddress((void**)&wb1h, g_wb1h); cudaGetSymbolAddress((void**)&wb1l, g_wb1l);
    cudaGetSymbolAddress((void**)&wb2h, g_wb2h); cudaGetSymbolAddress((void**)&wb2l, g_wb2l);
    cudaGetSymbolAddress((void**)&wb3h, g_wb3h); cudaGetSymbolAddress((void**)&wb3l, g_wb3l);

    cudaFuncSetAttribute(k_edge_mma, cudaFuncAttributeMaxDynamicSharedMemorySize, SMEM_MM);

    k_init<<<(N_NODES * HDIM + 127) / 128, 128>>>();
    k_wconv<<<128, 256>>>(Wv1, wv1h, wv1l, 128, 128, 4, 256, 0);
    k_wconv<<<64,  256>>>(Wv2, wv2h, wv2l, 128, 128, 2, 128, 0);
    k_wconv<<<64,  256>>>(Wv3, wv3h, wv3l, 128, 128, 2, 128, 0);
    k_wconv<<<128, 256>>>(Wb1, wb1h, wb1l, 128, 128, 4, 384, 128);
    k_wconv<<<64,  256>>>(Wb2, wb2h, wb2l, 128, 128, 2, 128, 0);
    k_wconv<<<8,   256>>>(Wb3, wb3h, wb3l, 16, 4, 2, 128, 0);
    k_pre<<<(N_NODES + 63) / 64, 128>>>(hV, Wb1, bb1);

    int egrid = (N_EDGES + 127) / 128;   // 4688
    k_edge_mma<<<egrid, 256, SMEM_MM>>>(1, hE, cid, bb2, bb3, bb1);  // bias MLP
    k_edge_mma<<<egrid, 256, SMEM_MM>>>(0, hE, cid, bv2, bv3, bv1);  // value MLP
    k_out<<<(N_NODES + 63) / 64, 128>>>(Wo, out);
}

// round 7
// speedup vs baseline: 3.3951x; 1.2203x over previous
#include <cuda_runtime.h>
#include <cuda_bf16.h>
#include <math.h>
#include <cstdint>

#define N_NODES 20000
#define N_EDGES 600000
#define HDIM 128
#define NHEADS 4
#define EB 4688   // ceil(600000/128)

// ---------------- scratch -----------------------------------------------------
__device__ float    g_P[N_NODES * HDIM];
__device__ float    g_num[N_NODES * HDIM];
__device__ float    g_den[N_NODES * NHEADS];
__device__ unsigned g_menc[N_NODES * NHEADS];
__device__ float    g_wlog[(size_t)N_EDGES * NHEADS];

// pre-split, pre-swizzled hE tiles: [block][chunk][16KB]
__device__ __align__(16) char g_hEh[(size_t)EB * 4 * 16384];
__device__ __align__(16) char g_hEl[(size_t)EB * 4 * 16384];

__device__ __align__(16) __nv_bfloat16 g_wv1h[32768], g_wv1l[32768];
__device__ __align__(16) __nv_bfloat16 g_wv2h[16384], g_wv2l[16384];
__device__ __align__(16) __nv_bfloat16 g_wv3h[16384], g_wv3l[16384];
__device__ __align__(16) __nv_bfloat16 g_wb1h[32768], g_wb1l[32768];
__device__ __align__(16) __nv_bfloat16 g_wb2h[16384], g_wb2l[16384];
__device__ __align__(16) __nv_bfloat16 g_wb3h[2048],  g_wb3l[2048];

// ---------------- helpers -----------------------------------------------------
__device__ __forceinline__ float gelu_f(float x) {
    return 0.5f * x * (1.0f + erff(x * 0.70710678118654752440f));
}
__device__ __forceinline__ unsigned fenc(float x) {
    unsigned b = __float_as_uint(x);
    return (b & 0x80000000u) ? ~b : (b | 0x80000000u);
}
__device__ __forceinline__ float fdec(unsigned e) {
    return __uint_as_float((e & 0x80000000u) ? (e & 0x7FFFFFFFu) : ~e);
}
#define ENC_NEG_INF 0x007FFFFFu

__device__ __forceinline__ void split2(float a, float b, unsigned &hi, unsigned &lo) {
    __nv_bfloat16 ha = __float2bfloat16(a), hb = __float2bfloat16(b);
    float ra = a - __bfloat162float(ha), rb = b - __bfloat162float(hb);
    __nv_bfloat162 th; th.x = ha; th.y = hb;
    __nv_bfloat162 tl = __floats2bfloat162_rn(ra, rb);
    hi = *reinterpret_cast<unsigned*>(&th);
    lo = *reinterpret_cast<unsigned*>(&tl);
}
__device__ __forceinline__ uint32_t smem_to_u32(const void* p) {
    uint32_t a;
    asm("{ .reg .u64 t; cvta.to.shared.u64 t, %1; cvt.u32.u64 %0, t; }" : "=r"(a) : "l"(p));
    return a;
}
__device__ __forceinline__ unsigned sw128(unsigned byte) {
    return byte ^ ((byte >> 3) & 0x70);
}

// ---------------- cp.async (base ISA) ------------------------------------------
__device__ __forceinline__ void cp16(uint32_t dst, const void* src) {
    asm volatile("cp.async.cg.shared.global [%0], [%1], 16;" :: "r"(dst), "l"(src));
}
#define CP_COMMIT() asm volatile("cp.async.commit_group;" ::: "memory")
#define CP_WAIT0()  asm volatile("cp.async.wait_group 0;" ::: "memory")
#define CP_WAIT1()  asm volatile("cp.async.wait_group 1;" ::: "memory")

// copy one 16KB tile (raw bytes, layout-preserving), 256 threads
__device__ __forceinline__ void cpa16k(uint32_t dst, const char* src, int tid) {
#pragma unroll
    for (int j = 0; j < 4; ++j)
        cp16(dst + tid * 16 + j * 4096, src + tid * 16 + j * 4096);
}

// ---------------- mma.sync primitives ------------------------------------------
__device__ __forceinline__ void ldsm4(unsigned r[4], uint32_t addr) {
    asm volatile("ldmatrix.sync.aligned.m8n8.x4.shared.b16 {%0,%1,%2,%3}, [%4];"
        : "=r"(r[0]), "=r"(r[1]), "=r"(r[2]), "=r"(r[3]) : "r"(addr));
}
__device__ __forceinline__ void mma_bf16(float c[4], const unsigned a[4], const unsigned b[2]) {
    asm volatile("mma.sync.aligned.m16n8k16.row.col.f32.bf16.bf16.f32 "
        "{%0,%1,%2,%3}, {%4,%5,%6,%7}, {%8,%9}, {%0,%1,%2,%3};"
        : "+f"(c[0]), "+f"(c[1]), "+f"(c[2]), "+f"(c[3])
        : "r"(a[0]), "r"(a[1]), "r"(a[2]), "r"(a[3]), "r"(b[0]), "r"(b[1]));
}

// smem byte offsets
#define OFF_CE   0
#define OFF_SEW  512
#define OFF_B0   4096
#define OFF_B1   36864
#define OFF_A0   69632
#define OFF_A1   102400
#define OFF_T0   135168
#define OFF_T1   69632          /* aliases A0/A1 (dead after L1) */
#define SMEM_MM  200704

// one K=64 chunk, 3-term split (hh, hl, lh); tiles 128x64 bf16 SW128 (128B pitch)
__device__ __forceinline__ void chunk_mma(float acc[4][4][4],
                                          uint32_t Ah, uint32_t Al,
                                          uint32_t Bh, uint32_t Bl,
                                          int wm, int wn, int lid) {
    int g = lid >> 3, r = lid & 7;
    int am = (g & 1) * 8 + r, ak = (g >> 1) * 8;
    int bn = (g >> 1) * 8 + r, bk = (g & 1) * 8;
#pragma unroll
    for (int ks = 0; ks < 4; ++ks) {
        int kb = ks * 16;
        unsigned Af[2][4][4], Bf[2][4][2];
#pragma unroll
        for (int s = 0; s < 2; ++s) {
            uint32_t Ab = s ? Al : Ah;
#pragma unroll
            for (int ms = 0; ms < 4; ++ms) {
                unsigned byte = (unsigned)((wm * 64 + ms * 16 + am) * 128 + (kb + ak) * 2);
                ldsm4(Af[s][ms], Ab + sw128(byte));
            }
            uint32_t Bb = s ? Bl : Bh;
#pragma unroll
            for (int np = 0; np < 2; ++np) {
                unsigned byte = (unsigned)((wn * 32 + np * 16 + bn) * 128 + (kb + bk) * 2);
                unsigned t[4];
                ldsm4(t, Bb + sw128(byte));
                Bf[s][np*2][0] = t[0]; Bf[s][np*2][1] = t[1];
                Bf[s][np*2+1][0] = t[2]; Bf[s][np*2+1][1] = t[3];
            }
        }
#pragma unroll
        for (int ms = 0; ms < 4; ++ms)
#pragma unroll
            for (int ns = 0; ns < 4; ++ns) {
                mma_bf16(acc[ms][ns], Af[0][ms], Bf[0][ns]);
                mma_bf16(acc[ms][ns], Af[0][ms], Bf[1][ns]);
                mma_bf16(acc[ms][ns], Af[1][ms], Bf[0][ns]);
            }
    }
}

// logits variant: n0-7 only, B tile 16-row padded
__device__ __forceinline__ void chunk_mma_log(float accl[4][4],
                                              uint32_t Ah, uint32_t Al,
                                              uint32_t Bh, uint32_t Bl,
                                              int wm, int lid) {
    int g = lid >> 3, r = lid & 7;
    int am = (g & 1) * 8 + r, ak = (g >> 1) * 8;
    int bn = (g >> 1) * 8 + r, bk = (g & 1) * 8;
#pragma unroll
    for (int ks = 0; ks < 4; ++ks) {
        int kb = ks * 16;
        unsigned Af[2][4][4], Bf[2][2];
#pragma unroll
        for (int s = 0; s < 2; ++s) {
            uint32_t Ab = s ? Al : Ah;
#pragma unroll
            for (int ms = 0; ms < 4; ++ms) {
                unsigned byte = (unsigned)((wm * 64 + ms * 16 + am) * 128 + (kb + ak) * 2);
                ldsm4(Af[s][ms], Ab + sw128(byte));
            }
            unsigned byte = (unsigned)(bn * 128 + (kb + bk) * 2);
            unsigned t[4];
            ldsm4(t, (s ? Bl : Bh) + sw128(byte));
            Bf[s][0] = t[0]; Bf[s][1] = t[1];
        }
#pragma unroll
        for (int ms = 0; ms < 4; ++ms) {
            mma_bf16(accl[ms], Af[0][ms], Bf[0]);
            mma_bf16(accl[ms], Af[0][ms], Bf[1]);
            mma_bf16(accl[ms], Af[1][ms], Bf[0]);
        }
    }
}

// acc + add -> gelu -> split -> T tiles (hi @ +ch*16K, lo @ +32K+ch*16K)
__device__ __forceinline__ void epi_store(float acc[4][4][4], char* T,
                                          const float* __restrict__ addv,
                                          const int* __restrict__ ce, bool perrow,
                                          int wm, int wn, int lid) {
#pragma unroll
    for (int ms = 0; ms < 4; ++ms) {
        int r0 = wm * 64 + ms * 16 + (lid >> 2), r1 = r0 + 8;
#pragma unroll
        for (int ns = 0; ns < 4; ++ns) {
            int n = wn * 32 + ns * 8 + (lid & 3) * 2;
            const float* a0 = perrow ? (addv + (size_t)ce[r0] * 128 + n) : (addv + n);
            const float* a1 = perrow ? (addv + (size_t)ce[r1] * 128 + n) : (addv + n);
            float o0 = gelu_f(acc[ms][ns][0] + a0[0]);
            float o1 = gelu_f(acc[ms][ns][1] + a0[1]);
            float o2 = gelu_f(acc[ms][ns][2] + a1[0]);
            float o3 = gelu_f(acc[ms][ns][3] + a1[1]);
            unsigned h01, l01, h23, l23;
            split2(o0, o1, h01, l01);
            split2(o2, o3, h23, l23);
            int ch = n >> 6, kk = n & 63;
            unsigned s0 = sw128((unsigned)(r0 * 128 + kk * 2));
            unsigned s1 = sw128((unsigned)(r1 * 128 + kk * 2));
            char* th = T + ch * 16384;
            *(unsigned*)(th + s0) = h01;          *(unsigned*)(th + s1) = h23;
            *(unsigned*)(th + 32768 + s0) = l01;  *(unsigned*)(th + 32768 + s1) = l23;
        }
    }
}

// ---------------- setup kernels -----------------------------------------------
extern "C" __global__ void __launch_bounds__(128)
k_init() {
    int i = blockIdx.x * blockDim.x + threadIdx.x;
    if (i < N_NODES * HDIM) g_num[i] = 0.0f;
    if (i < N_NODES * NHEADS) { g_den[i] = 0.0f; g_menc[i] = ENC_NEG_INF; }
}

// hE -> pre-swizzled bf16 hi/lo tiles (one float4 per thread-iter)
extern "C" __global__ void __launch_bounds__(256)
k_esplit(const float* __restrict__ hE) {
    const float4* hE4 = reinterpret_cast<const float4*>(hE);
    const size_t total = (size_t)EB * 128 * 64;
#pragma unroll
    for (int j = 0; j < 4; ++j) {
        size_t idx = (size_t)blockIdx.x * 1024 + j * 256 + threadIdx.x;
        if (idx >= total) continue;
        size_t e = idx >> 6; int q = (int)(idx & 63);
        int c = q >> 4, q15 = q & 15;
        int m = (int)(e & 127); size_t eb = e >> 7;
        float4 v = make_float4(0.f, 0.f, 0.f, 0.f);
        if (e < N_EDGES) v = hE4[e * 64 + (size_t)q];
        unsigned sw = sw128((unsigned)(m * 128 + q15 * 8));
        size_t tb = (eb * 4 + (size_t)c) * 16384;
        unsigned h01, l01, h23, l23;
        split2(v.x, v.y, h01, l01);
        split2(v.z, v.w, h23, l23);
        *(uint2*)(g_hEh + tb + sw) = make_uint2(h01, h23);
        *(uint2*)(g_hEl + tb + sw) = make_uint2(l01, l23);
    }
}

extern "C" __global__ void __launch_bounds__(256)
k_wconv(const float* __restrict__ W, __nv_bfloat16* __restrict__ hi,
        __nv_bfloat16* __restrict__ lo, int nrows_pad, int nrows_real,
        int nchunks, int rstride, int coff) {
    int idx = blockIdx.x * 256 + threadIdx.x;
    int tile = nrows_pad * 64;
    if (idx >= tile * nchunks) return;
    int c = idx / tile, rem = idx % tile;
    int n = rem / 64, kk = rem % 64;
    float x = (n < nrows_real) ? W[n * rstride + coff + c * 64 + kk] : 0.0f;
    __nv_bfloat16 h = __float2bfloat16(x);
    float r = x - __bfloat162float(h);
    unsigned sw = sw128((unsigned)(n * 128 + kk * 2));
    hi[c * tile + sw / 2] = h;
    lo[c * tile + sw / 2] = __float2bfloat16(r);
}

template<int K, int XP>
__device__ __forceinline__ void gemm_stage(float acc[64], const float* __restrict__ wrow,
                                           const float* __restrict__ xs) {
#pragma unroll 1
    for (int k = 0; k < K; k += 4) {
        float4 wv = *reinterpret_cast<const float4*>(wrow + k);
#pragma unroll
        for (int e = 0; e < 64; ++e) {
            float4 xv = *reinterpret_cast<const float4*>(xs + e * XP + k);
            acc[e] = fmaf(wv.x, xv.x, acc[e]);
            acc[e] = fmaf(wv.y, xv.y, acc[e]);
            acc[e] = fmaf(wv.z, xv.z, acc[e]);
            acc[e] = fmaf(wv.w, xv.w, acc[e]);
        }
    }
}

extern "C" __global__ void __launch_bounds__(128)
k_pre(const float* __restrict__ hV, const float* __restrict__ Wb1,
      const float* __restrict__ bb1) {
    __shared__ float xs[64 * HDIM];
    int j = threadIdx.x;
    int n0 = blockIdx.x * 64;
    int cnt = N_NODES - n0; if (cnt > 64) cnt = 64;
    const float4* src = reinterpret_cast<const float4*>(hV + (size_t)n0 * HDIM);
    float4* dst = reinterpret_cast<float4*>(xs);
    for (int i = j; i < 64 * HDIM / 4; i += 128) {
        int n = i / (HDIM / 4);
        dst[i] = (n < cnt) ? src[i] : make_float4(0.f, 0.f, 0.f, 0.f);
    }
    __syncthreads();
    float acc[64];
    float b = bb1[j];
#pragma unroll
    for (int e = 0; e < 64; ++e) acc[e] = b;
    gemm_stage<HDIM, HDIM>(acc, Wb1 + j * 384, xs);
#pragma unroll
    for (int e = 0; e < 64; ++e)
        if (e < cnt) g_P[(size_t)(n0 + e) * HDIM + j] = acc[e];
}

// ---------------- pipelined HMMA edge kernel -----------------------------------
extern "C" __global__ void __launch_bounds__(256)
k_edge_mma(int mode, const int* __restrict__ cid,
           const float* __restrict__ b2, const float* __restrict__ b3,
           const float* __restrict__ b1) {
    extern __shared__ char sm[];
    uint32_t smb = smem_to_u32(sm);
    int tid = threadIdx.x, wid = tid >> 5, lid = tid & 31;
    int wm = wid & 1, wn = wid >> 1;
    size_t e0 = (size_t)blockIdx.x * 128;
    size_t eb = (size_t)blockIdx.x;
    int* ce = (int*)(sm + OFF_CE);
    float* sew = (float*)(sm + OFF_SEW);
    if (tid < 128) ce[tid] = (e0 + tid < N_EDGES) ? cid[e0 + tid] : 0;

    const char* W1h = (const char*)(mode ? g_wb1h : g_wv1h);
    const char* W1l = (const char*)(mode ? g_wb1l : g_wv1l);
    const char* W2h = (const char*)(mode ? g_wb2h : g_wv2h);
    const char* W2l = (const char*)(mode ? g_wb2l : g_wv2l);

    float acc[4][4][4];
#pragma unroll
    for (int i = 0; i < 4; ++i)
#pragma unroll
        for (int j2 = 0; j2 < 4; ++j2)
#pragma unroll
            for (int k = 0; k < 4; ++k) acc[i][j2][k] = 0.f;

    // ---- L1: hE @ W1^T (K=256, 4 chunks, cp.async double-buffered) ----
    cpa16k(smb + OFF_A0,         g_hEh + eb * 4 * 16384, tid);
    cpa16k(smb + OFF_A0 + 16384, g_hEl + eb * 4 * 16384, tid);
    cpa16k(smb + OFF_B0,         W1h, tid);
    cpa16k(smb + OFF_B0 + 16384, W1l, tid);
    CP_COMMIT();
    for (int c = 0; c < 4; ++c) {
        if (c < 3) {
            uint32_t A = smb + (((c + 1) & 1) ? OFF_A1 : OFF_A0);
            uint32_t B = smb + (((c + 1) & 1) ? OFF_B1 : OFF_B0);
            cpa16k(A,         g_hEh + (eb * 4 + c + 1) * 16384, tid);
            cpa16k(A + 16384, g_hEl + (eb * 4 + c + 1) * 16384, tid);
            cpa16k(B,         W1h + (size_t)(c + 1) * 16384, tid);
            cpa16k(B + 16384, W1l + (size_t)(c + 1) * 16384, tid);
            CP_COMMIT();
            CP_WAIT1();
        } else CP_WAIT0();
        __syncthreads();
        uint32_t A = smb + ((c & 1) ? OFF_A1 : OFF_A0);
        uint32_t B = smb + ((c & 1) ? OFF_B1 : OFF_B0);
        chunk_mma(acc, A, A + 16384, B, B + 16384, wm, wn, lid);
        __syncthreads();
    }
    epi_store(acc, sm + OFF_T0, mode ? g_P : b1, ce, mode != 0, wm, wn, lid);
    __syncthreads();

    // ---- L2: t1 @ W2^T (K=128, 2 chunks) ----
#pragma unroll
    for (int i = 0; i < 4; ++i)
#pragma unroll
        for (int j2 = 0; j2 < 4; ++j2)
#pragma unroll
            for (int k = 0; k < 4; ++k) acc[i][j2][k] = 0.f;
    cpa16k(smb + OFF_B0,         W2h, tid);
    cpa16k(smb + OFF_B0 + 16384, W2l, tid);
    CP_COMMIT();
    for (int c = 0; c < 2; ++c) {
        if (c == 0) {
            cpa16k(smb + OFF_B1,         W2h + 16384, tid);
            cpa16k(smb + OFF_B1 + 16384, W2l + 16384, tid);
            CP_COMMIT();
            CP_WAIT1();
        } else CP_WAIT0();
        __syncthreads();
        uint32_t T = smb + OFF_T0 + c * 16384;
        uint32_t B = smb + (c ? OFF_B1 : OFF_B0);
        chunk_mma(acc, T, T + 32768, B, B + 16384, wm, wn, lid);
        __syncthreads();
    }
    epi_store(acc, sm + OFF_T1, b2, ce, false, wm, wn, lid);
    __syncthreads();

    // ---- L3 ----
    if (mode) {
        // logits = t2 @ Wb3p^T (16-row padded chunks, 2KB each)
        const char* W3h = (const char*)g_wb3h;
        const char* W3l = (const char*)g_wb3l;
        if (tid < 128) {
            cp16(smb + OFF_B0 + tid * 16, W3h + tid * 16);
            cp16(smb + OFF_B1 + tid * 16, W3h + 2048 + tid * 16);
        } else {
            int t = tid - 128;
            cp16(smb + OFF_B0 + 16384 + t * 16, W3l + t * 16);
            cp16(smb + OFF_B1 + 16384 + t * 16, W3l + 2048 + t * 16);
        }
        CP_COMMIT(); CP_WAIT0();
        __syncthreads();
        float accl[4][4];
#pragma unroll
        for (int i = 0; i < 4; ++i)
#pragma unroll
            for (int k = 0; k < 4; ++k) accl[i][k] = 0.f;
        if (wn == 0) {
            uint32_t T = smb + OFF_T1;
            chunk_mma_log(accl, T,         T + 32768,         smb + OFF_B0, smb + OFF_B0 + 16384, wm, lid);
            chunk_mma_log(accl, T + 16384, T + 32768 + 16384, smb + OFF_B1, smb + OFF_B1 + 16384, wm, lid);
        }
        if (wn == 0 && (lid & 3) < 2) {
            const float rs = 0.17677669529663687f;  // 1/sqrt(32)
            int n = (lid & 3) * 2;
            float bn0 = b3[n], bn1 = b3[n + 1];
#pragma unroll
            for (int ms = 0; ms < 4; ++ms) {
                int r0 = wm * 64 + ms * 16 + (lid >> 2), r1 = r0 + 8;
                if (e0 + r0 < N_EDGES) {
                    float w0 = (accl[ms][0] + bn0) * rs, w1 = (accl[ms][1] + bn1) * rs;
                    g_wlog[(e0 + r0) * 4 + n] = w0;
                    g_wlog[(e0 + r0) * 4 + n + 1] = w1;
                    atomicMax(&g_menc[(size_t)ce[r0] * 4 + n], fenc(w0));
                    atomicMax(&g_menc[(size_t)ce[r0] * 4 + n + 1], fenc(w1));
                }
                if (e0 + r1 < N_EDGES) {
                    float w2 = (accl[ms][2] + bn0) * rs, w3 = (accl[ms][3] + bn1) * rs;
                    g_wlog[(e0 + r1) * 4 + n] = w2;
                    g_wlog[(e0 + r1) * 4 + n + 1] = w3;
                    atomicMax(&g_menc[(size_t)ce[r1] * 4 + n], fenc(w2));
                    atomicMax(&g_menc[(size_t)ce[r1] * 4 + n + 1], fenc(w3));
                }
            }
        }
    } else {
        // V = t2 @ Wv3^T; exp-weighted scatter
#pragma unroll
        for (int i = 0; i < 4; ++i)
#pragma unroll
            for (int j2 = 0; j2 < 4; ++j2)
#pragma unroll
                for (int k = 0; k < 4; ++k) acc[i][j2][k] = 0.f;
        const char* W3h = (const char*)g_wv3h;
        const char* W3l = (const char*)g_wv3l;
        cpa16k(smb + OFF_B0,         W3h, tid);
        cpa16k(smb + OFF_B0 + 16384, W3l, tid);
        CP_COMMIT();
        for (int c = 0; c < 2; ++c) {
            if (c == 0) {
                cpa16k(smb + OFF_B1,         W3h + 16384, tid);
                cpa16k(smb + OFF_B1 + 16384, W3l + 16384, tid);
                CP_COMMIT();
                CP_WAIT1();
            } else CP_WAIT0();
            __syncthreads();
            uint32_t T = smb + OFF_T1 + c * 16384;
            uint32_t B = smb + (c ? OFF_B1 : OFF_B0);
            chunk_mma(acc, T, T + 32768, B, B + 16384, wm, wn, lid);
            __syncthreads();
        }
        // per-edge softmax weights (+ denominator)
        if (tid < 128) {
            bool v = (e0 + tid) < N_EDGES;
            int cn = ce[tid];
#pragma unroll
            for (int h = 0; h < 4; ++h) {
                float ew = 0.f;
                if (v) {
                    float w = g_wlog[(e0 + tid) * 4 + h];
                    float m = fdec(g_menc[(size_t)cn * 4 + h]);
                    ew = expf(w - m);
                    atomicAdd(&g_den[(size_t)cn * 4 + h], ew);
                }
                sew[tid * 4 + h] = ew;
            }
        }
        __syncthreads();
#pragma unroll
        for (int ms = 0; ms < 4; ++ms) {
            int r0 = wm * 64 + ms * 16 + (lid >> 2), r1 = r0 + 8;
            float ew0 = sew[r0 * 4 + wn], ew1 = sew[r1 * 4 + wn];
            bool v0 = (e0 + r0) < N_EDGES, v1 = (e0 + r1) < N_EDGES;
            float* d0 = g_num + (size_t)ce[r0] * 128;
            float* d1 = g_num + (size_t)ce[r1] * 128;
#pragma unroll
            for (int ns = 0; ns < 4; ++ns) {
                int n = wn * 32 + ns * 8 + (lid & 3) * 2;
                float bn0 = b3[n], bn1 = b3[n + 1];
                if (v0) {
                    atomicAdd(d0 + n,     ew0 * (acc[ms][ns][0] + bn0));
                    atomicAdd(d0 + n + 1, ew0 * (acc[ms][ns][1] + bn1));
                }
                if (v1) {
                    atomicAdd(d1 + n,     ew1 * (acc[ms][ns][2] + bn0));
                    atomicAdd(d1 + n + 1, ew1 * (acc[ms][ns][3] + bn1));
                }
            }
        }
    }
}

// ---------------- output projection --------------------------------------------
extern "C" __global__ void __launch_bounds__(128)
k_out(const float* __restrict__ Wo, float* __restrict__ out) {
    __shared__ float xs[64 * HDIM];
    int j = threadIdx.x;
    int n0 = blockIdx.x * 64;
    int cnt = N_NODES - n0; if (cnt > 64) cnt = 64;
    for (int i = j; i < 64 * HDIM; i += 128) {
        int n = i >> 7, c = i & 127;
        float v = 0.f;
        if (n < cnt) {
            float d = g_den[(size_t)(n0 + n) * NHEADS + (c >> 5)];
            float nm = g_num[(size_t)(n0 + n) * HDIM + c];
            v = (d > 0.f) ? nm / d : 0.f;
        }
        xs[i] = v;
    }
    __syncthreads();
    float acc[64];
#pragma unroll
    for (int e = 0; e < 64; ++e) acc[e] = 0.f;
    gemm_stage<HDIM, HDIM>(acc, Wo + j * HDIM, xs);
#pragma unroll
    for (int e = 0; e < 64; ++e)
        if (e < cnt) out[(size_t)(n0 + e) * HDIM + j] = acc[e];
}

// ---------------- launch --------------------------------------------------------
extern "C" void kernel_launch(void* const* d_in, const int* in_sizes, int n_in,
                              void* d_out, int out_size) {
    const float* hV  = (const float*)d_in[0];
    const float* hE  = (const float*)d_in[1];
    const float* Wv1 = (const float*)d_in[2];
    const float* bv1 = (const float*)d_in[3];
    const float* Wv2 = (const float*)d_in[4];
    const float* bv2 = (const float*)d_in[5];
    const float* Wv3 = (const float*)d_in[6];
    const float* bv3 = (const float*)d_in[7];
    const float* Wb1 = (const float*)d_in[8];
    const float* bb1 = (const float*)d_in[9];
    const float* Wb2 = (const float*)d_in[10];
    const float* bb2 = (const float*)d_in[11];
    const float* Wb3 = (const float*)d_in[12];
    const float* bb3 = (const float*)d_in[13];
    const float* Wo  = (const float*)d_in[14];
    const int*   cid = (const int*)d_in[15];
    float* out = (float*)d_out;

    __nv_bfloat16 *wv1h, *wv1l, *wv2h, *wv2l, *wv3h, *wv3l;
    __nv_bfloat16 *wb1h, *wb1l, *wb2h, *wb2l, *wb3h, *wb3l;
    cudaGetSymbolAddress((void**)&wv1h, g_wv1h); cudaGetSymbolAddress((void**)&wv1l, g_wv1l);
    cudaGetSymbolAddress((void**)&wv2h, g_wv2h); cudaGetSymbolAddress((void**)&wv2l, g_wv2l);
    cudaGetSymbolAddress((void**)&wv3h, g_wv3h); cudaGetSymbolAddress((void**)&wv3l, g_wv3l);
    cudaGetSymbolAddress((void**)&wb1h, g_wb1h); cudaGetSymbolAddress((void**)&wb1l, g_wb1l);
    cudaGetSymbolAddress((void**)&wb2h, g_wb2h); cudaGetSymbolAddress((void**)&wb2l, g_wb2l);
    cudaGetSymbolAddress((void**)&wb3h, g_wb3h); cudaGetSymbolAddress((void**)&wb3l, g_wb3l);

    cudaFuncSetAttribute(k_edge_mma, cudaFuncAttributeMaxDynamicSharedMemorySize, SMEM_MM);

    k_init<<<(N_NODES * HDIM + 127) / 128, 128>>>();
    k_wconv<<<128, 256>>>(Wv1, wv1h, wv1l, 128, 128, 4, 256, 0);
    k_wconv<<<64,  256>>>(Wv2, wv2h, wv2l, 128, 128, 2, 128, 0);
    k_wconv<<<64,  256>>>(Wv3, wv3h, wv3l, 128, 128, 2, 128, 0);
    k_wconv<<<128, 256>>>(Wb1, wb1h, wb1l, 128, 128, 4, 384, 128);
    k_wconv<<<64,  256>>>(Wb2, wb2h, wb2l, 128, 128, 2, 128, 0);
    k_wconv<<<8,   256>>>(Wb3, wb3h, wb3l, 16, 4, 2, 128, 0);
    k_esplit<<<(EB * 128 * 64 + 1023) / 1024, 256>>>(hE);
    k_pre<<<(N_NODES + 63) / 64, 128>>>(hV, Wb1, bb1);

    k_edge_mma<<<EB, 256, SMEM_MM>>>(1, cid, bb2, bb3, bb1);  // bias MLP
    k_edge_mma<<<EB, 256, SMEM_MM>>>(0, cid, bv2, bv3, bv1);  // value MLP
    k_out<<<(N_NODES + 63) / 64, 128>>>(Wo, out);
}